// round 7
// baseline (speedup 1.0000x reference)
#include <cuda_runtime.h>
#include <math.h>

#define NN 100000
#define EE 1600000
#define HH 128
#define GG 64
#define SCAN_BLOCKS 391            // ceil(NN/256)

// ---------------- scratch (device globals; allocation-free) ----------------
__device__ float g_dinv[NN];
__device__ int   g_deg[NN];
__device__ int   g_csr_off[NN + 1];
__device__ int   g_csr_pos[NN];
__device__ int   g_csr_src[EE];
__device__ int   g_part[SCAN_BLOCKS];
__device__ float g_h[NN * HH];
__device__ float g_zs[NN * HH];
__device__ float g_agg[NN * HH];
__device__ float g_sum[HH];
__device__ float g_sumsq[HH];
__device__ float g_scale[HH];
__device__ float g_shift[HH];
__device__ float g_esc[NN];
__device__ float g_sumexp;
__device__ int   g_gstart[GG + 1];
__device__ float g_pooled[GG * HH];

// ---------------- f32x2 helpers (Blackwell packed FFMA2) ----------------
__device__ __forceinline__ unsigned long long dup2(float v) {
    unsigned long long r;
    unsigned int b = __float_as_uint(v);
    asm("mov.b64 %0, {%1, %1};" : "=l"(r) : "r"(b));
    return r;
}
__device__ __forceinline__ void fma2(unsigned long long& d, unsigned long long a,
                                     unsigned long long b) {
    asm("fma.rn.f32x2 %0, %1, %2, %3;" : "=l"(d) : "l"(a), "l"(b), "l"(d));
}
__device__ __forceinline__ float2 unpack2(unsigned long long v) {
    float2 r;
    asm("mov.b64 {%0, %1}, %2;" : "=f"(r.x), "=f"(r.y) : "l"(v));
    return r;
}

// ---------------- init / degree ----------------
__global__ void k_init() {
    int i = blockIdx.x * blockDim.x + threadIdx.x;
    if (i < NN) g_deg[i] = 0;
    if (i == 0) g_sumexp = 0.0f;
}

__global__ void k_count(const int* __restrict__ edst) {
    int e = blockIdx.x * blockDim.x + threadIdx.x;
    if (e < EE) atomicAdd(&g_deg[edst[e]], 1);
}

__global__ void k_rsqrt() {
    int i = blockIdx.x * blockDim.x + threadIdx.x;
    if (i < NN) g_dinv[i] = rsqrtf((float)g_deg[i] + 1.0f);   // +1 self loop
}

// ---------------- CSR build ----------------
__global__ __launch_bounds__(256) void k_scan1() {
    __shared__ int sh[256];
    int i = blockIdx.x * 256 + threadIdx.x;
    sh[threadIdx.x] = (i < NN) ? g_deg[i] : 0;
    __syncthreads();
    for (int s = 128; s > 0; s >>= 1) {
        if (threadIdx.x < s) sh[threadIdx.x] += sh[threadIdx.x + s];
        __syncthreads();
    }
    if (threadIdx.x == 0) g_part[blockIdx.x] = sh[0];
}

__global__ void k_scan2() {
    if (threadIdx.x == 0) {
        int run = 0;
        for (int b = 0; b < SCAN_BLOCKS; b++) {
            int v = g_part[b];
            g_part[b] = run;
            run += v;
        }
        g_csr_off[NN] = run;    // == EE
    }
}

__global__ __launch_bounds__(256) void k_scan3() {
    __shared__ int sh[256];
    int i = blockIdx.x * 256 + threadIdx.x;
    int v = (i < NN) ? g_deg[i] : 0;
    sh[threadIdx.x] = v;
    __syncthreads();
    for (int s = 1; s < 256; s <<= 1) {
        int t = (threadIdx.x >= s) ? sh[threadIdx.x - s] : 0;
        __syncthreads();
        sh[threadIdx.x] += t;
        __syncthreads();
    }
    if (i < NN) {
        int excl = sh[threadIdx.x] - v + g_part[blockIdx.x];
        g_csr_off[i] = excl;
        g_csr_pos[i] = excl;
    }
}

__global__ __launch_bounds__(256) void k_fill(const int* __restrict__ esrc,
                                              const int* __restrict__ edst) {
    int e = blockIdx.x * blockDim.x + threadIdx.x;
    if (e >= EE) return;
    int d = edst[e];
    int p = atomicAdd(&g_csr_pos[d], 1);
    g_csr_src[p] = esrc[e];
}

// ---------------- GEMM: z = A(N,128) @ W(128,128) --------------------------
// BM=80, 5x8 microtile, FFMA2, 2 CTAs/SM.
// mode 0: g_zs = z*dinv[row];  g_agg = z*dinv^2 + bias[c]
// mode 1: fused attention score: g_esc[row]=exp(tanh(z+bias)·w2 + b2), += g_sumexp
#define BM 80
#define LDA 132
__global__ __launch_bounds__(256, 2) void k_gemm(
    const float* __restrict__ Ain, const float* __restrict__ W,
    const float* __restrict__ bias,
    const float* __restrict__ w2, const float* __restrict__ b2,
    int mode)
{
    const float* A = (Ain == nullptr) ? g_h : Ain;
    extern __shared__ float sm[];
    float* sW = sm;                 // 128*128
    float* sA = sm + HH * HH;       // BM*LDA
    __shared__ float sh_e;
    int tid = threadIdx.x;
    int row0 = blockIdx.x * BM;
    if (tid == 0) sh_e = 0.0f;

    // load W (16384 floats = 4096 float4)
    {
        const float4* W4 = (const float4*)W;
        float4* sW4 = (float4*)sW;
#pragma unroll
        for (int t = 0; t < 16; t++) sW4[tid + t * 256] = W4[tid + t * 256];
    }
    // load A tile (80 rows x 128 = 2560 float4)
    {
#pragma unroll
        for (int t = 0; t < 10; t++) {
            int idx = tid + t * 256;          // 0..2559
            int r = idx >> 5, c4 = idx & 31;
            int row = row0 + r;
            if (row < NN) {
                float4 v = *(const float4*)&A[(size_t)row * HH + c4 * 4];
                *(float4*)&sA[r * LDA + c4 * 4] = v;
            }
        }
    }
    __syncthreads();

    int tx = tid & 15, ty = tid >> 4;
    int cbase = tx * 8;
    unsigned long long acc[5][4];
#pragma unroll
    for (int i = 0; i < 5; i++)
#pragma unroll
        for (int j = 0; j < 4; j++) acc[i][j] = 0ull;

#pragma unroll 4
    for (int k0 = 0; k0 < HH; k0 += 4) {
        float4 a[5];
#pragma unroll
        for (int i = 0; i < 5; i++)
            a[i] = *(float4*)&sA[(ty + i * 16) * LDA + k0];
#pragma unroll
        for (int kk = 0; kk < 4; kk++) {
            ulonglong2 b0 = *(ulonglong2*)&sW[(k0 + kk) * HH + cbase];
            ulonglong2 b1 = *(ulonglong2*)&sW[(k0 + kk) * HH + cbase + 4];
#pragma unroll
            for (int i = 0; i < 5; i++) {
                unsigned long long ad = dup2((&a[i].x)[kk]);
                fma2(acc[i][0], ad, b0.x);
                fma2(acc[i][1], ad, b0.y);
                fma2(acc[i][2], ad, b1.x);
                fma2(acc[i][3], ad, b1.y);
            }
        }
    }

    float4 bv0 = ((const float4*)bias)[tx * 2];
    float4 bv1 = ((const float4*)bias)[tx * 2 + 1];
    float4 wv0, wv1;
    float b2v = 0.0f, esum = 0.0f;
    if (mode == 1) {
        wv0 = ((const float4*)w2)[tx * 2];
        wv1 = ((const float4*)w2)[tx * 2 + 1];
        b2v = b2[0];
    }

#pragma unroll
    for (int i = 0; i < 5; i++) {
        int row = row0 + ty + i * 16;
        float2 p0 = unpack2(acc[i][0]);
        float2 p1 = unpack2(acc[i][1]);
        float2 p2 = unpack2(acc[i][2]);
        float2 p3 = unpack2(acc[i][3]);
        float z[8] = {p0.x, p0.y, p1.x, p1.y, p2.x, p2.y, p3.x, p3.y};
        if (mode == 0) {
            if (row < NN) {
                size_t off = (size_t)row * HH + cbase;
                float di = g_dinv[row];
                float di2 = di * di;
                float4 z0 = make_float4(z[0] * di, z[1] * di, z[2] * di, z[3] * di);
                float4 z1 = make_float4(z[4] * di, z[5] * di, z[6] * di, z[7] * di);
                *(float4*)&g_zs[off]     = z0;
                *(float4*)&g_zs[off + 4] = z1;
                float4 q0 = make_float4(z[0] * di2 + bv0.x, z[1] * di2 + bv0.y,
                                        z[2] * di2 + bv0.z, z[3] * di2 + bv0.w);
                float4 q1 = make_float4(z[4] * di2 + bv1.x, z[5] * di2 + bv1.y,
                                        z[6] * di2 + bv1.z, z[7] * di2 + bv1.w);
                *(float4*)&g_agg[off]     = q0;
                *(float4*)&g_agg[off + 4] = q1;
            }
        } else {
            float t0 = tanhf(z[0] + bv0.x), t1 = tanhf(z[1] + bv0.y);
            float t2 = tanhf(z[2] + bv0.z), t3 = tanhf(z[3] + bv0.w);
            float t4 = tanhf(z[4] + bv1.x), t5 = tanhf(z[5] + bv1.y);
            float t6 = tanhf(z[6] + bv1.z), t7 = tanhf(z[7] + bv1.w);
            float part = t0 * wv0.x + t1 * wv0.y + t2 * wv0.z + t3 * wv0.w
                       + t4 * wv1.x + t5 * wv1.y + t6 * wv1.z + t7 * wv1.w;
#pragma unroll
            for (int off16 = 8; off16; off16 >>= 1)
                part += __shfl_xor_sync(0xffffffffu, part, off16);
            if ((tx == 0) && row < NN) {
                float e = expf(part + b2v);
                g_esc[row] = e;
                esum += e;
            }
        }
    }

    if (mode == 1) {
        if (tx == 0) atomicAdd(&sh_e, esum);
        __syncthreads();
        if (tid == 0) atomicAdd(&g_sumexp, sh_e);
    }
}

// ---------------- aggregate (CSR gather) + fused BN stats ----------------
// one warp per dst node (grid-stride), R4-proven inner loop
#define AGG_BLOCKS 1184
__global__ __launch_bounds__(256) void k_aggregate() {
    int tid = threadIdx.x;
    int lane = tid & 31, warp = tid >> 5;
    int gw = blockIdx.x * 8 + warp;
    int nw = gridDim.x * 8;
    float4 s4 = make_float4(0, 0, 0, 0);
    float4 q4 = make_float4(0, 0, 0, 0);

    for (int node = gw; node < NN; node += nw) {
        int beg = g_csr_off[node], end = g_csr_off[node + 1];
        float4 acc = make_float4(0, 0, 0, 0);
        for (int base = beg; base < end; base += 32) {
            int idx = base + lane;
            int s = (idx < end) ? g_csr_src[idx] : 0;
            int cnt = min(32, end - base);
            for (int j = 0; j < cnt; j++) {
                int ss = __shfl_sync(0xffffffffu, s, j);
                float4 v = *(const float4*)&g_zs[(size_t)ss * HH + lane * 4];
                acc.x += v.x; acc.y += v.y; acc.z += v.z; acc.w += v.w;
            }
        }
        float di = g_dinv[node];
        float* rowp = &g_agg[(size_t)node * HH + lane * 4];
        float4 r = *(float4*)rowp;
        r.x += di * acc.x; r.y += di * acc.y; r.z += di * acc.z; r.w += di * acc.w;
        *(float4*)rowp = r;
        s4.x += r.x; s4.y += r.y; s4.z += r.z; s4.w += r.w;
        q4.x += r.x * r.x; q4.y += r.y * r.y; q4.z += r.z * r.z; q4.w += r.w * r.w;
    }

    __shared__ float sh[8][HH];
    ((float4*)sh[warp])[lane] = s4;
    __syncthreads();
    if (tid < HH) {
        float t = 0.0f;
#pragma unroll
        for (int w = 0; w < 8; w++) t += sh[w][tid];
        atomicAdd(&g_sum[tid], t);
    }
    __syncthreads();
    ((float4*)sh[warp])[lane] = q4;
    __syncthreads();
    if (tid < HH) {
        float t = 0.0f;
#pragma unroll
        for (int w = 0; w < 8; w++) t += sh[w][tid];
        atomicAdd(&g_sumsq[tid], t);
    }
}

// ---------------- batchnorm finalize / apply ----------------
__global__ void k_bnfin(const float* __restrict__ gamma, const float* __restrict__ beta) {
    int c = threadIdx.x;
    float mean = g_sum[c] / (float)NN;
    float var = g_sumsq[c] / (float)NN - mean * mean;
    float sc = rsqrtf(var + 1e-5f) * gamma[c];
    g_scale[c] = sc;
    g_shift[c] = beta[c] - mean * sc;
    g_sum[c] = 0.0f;
    g_sumsq[c] = 0.0f;
}

__global__ __launch_bounds__(256) void k_apply(int residual) {
    int i4 = blockIdx.x * blockDim.x + threadIdx.x;   // over NN*32 float4s
    if (i4 >= NN * 32) return;
    int c4 = i4 & 31;
    float4 v  = ((const float4*)g_agg)[i4];
    float4 sc = ((const float4*)g_scale)[c4];
    float4 sf = ((const float4*)g_shift)[c4];
    float4 r;
    r.x = fmaxf(v.x * sc.x + sf.x, 0.0f);
    r.y = fmaxf(v.y * sc.y + sf.y, 0.0f);
    r.z = fmaxf(v.z * sc.z + sf.z, 0.0f);
    r.w = fmaxf(v.w * sc.w + sf.w, 0.0f);
    if (residual) {
        float4 hv = ((const float4*)g_h)[i4];
        r.x += hv.x; r.y += hv.y; r.z += hv.z; r.w += hv.w;
    }
    ((float4*)g_h)[i4] = r;
}

// ---------------- graph offsets + zero pooled ----------------
__global__ void k_gstart(const int* __restrict__ batch) {
    int g = blockIdx.x, c = threadIdx.x;
    g_pooled[g * HH + c] = 0.0f;
    if (c == 0) {
        int lo = 0, hi = NN;
        while (lo < hi) {
            int m = (lo + hi) >> 1;
            if (batch[m] < g) lo = m + 1; else hi = m;
        }
        g_gstart[g] = lo;
        if (g == 0) g_gstart[GG] = NN;
    }
}

// ---------------- pooling (weighted sums) ----------------
__global__ void k_pool() {
    int g = blockIdx.x >> 3;
    int part = blockIdx.x & 7;
    int s = g_gstart[g], e = g_gstart[g + 1];
    int c = threadIdx.x;
    float acc = 0.0f;
    for (int r = s + part; r < e; r += 8)
        acc += g_h[(size_t)r * HH + c] * g_esc[r];
    atomicAdd(&g_pooled[g * HH + c], acc);
}

// ---------------- final MLP ----------------
__global__ void k_mlp(const float* __restrict__ W1, const float* __restrict__ b1,
                      const float* __restrict__ W2, const float* __restrict__ b2,
                      float* __restrict__ out)
{
    __shared__ float p[HH];
    __shared__ float t[HH];
    int g = blockIdx.x, c = threadIdx.x;
    int cnt = g_gstart[g + 1] - g_gstart[g];
    if (cnt < 1) cnt = 1;
    float inv = 1.0f / (g_sumexp * (float)cnt);
    p[c] = g_pooled[g * HH + c] * inv;
    __syncthreads();
    float acc = b1[c];
    for (int k = 0; k < HH; k++) acc += p[k] * W1[k * HH + c];
    t[c] = fmaxf(acc, 0.0f);
    __syncthreads();
    float acc2 = b2[c];
    for (int k = 0; k < HH; k++) acc2 += t[k] * W2[k * HH + c];
    out[g * HH + c] = acc2;
}

// ---------------- host ----------------
extern "C" void kernel_launch(void* const* d_in, const int* in_sizes, int n_in,
                              void* d_out, int out_size)
{
    const float* x      = (const float*)d_in[0];
    const int*   ei     = (const int*)d_in[1];   // [2, E] int32
    const int*   batch  = (const int*)d_in[2];
    const float* conv_w = (const float*)d_in[3];       // [3,128,128]
    const float* conv_b = (const float*)d_in[4];       // [3,128]
    const float* bn_g   = (const float*)d_in[5];
    const float* bn_b   = (const float*)d_in[6];
    const float* aw1    = (const float*)d_in[7];
    const float* ab1    = (const float*)d_in[8];
    const float* aw2    = (const float*)d_in[9];
    const float* ab2    = (const float*)d_in[10];
    const float* pw1    = (const float*)d_in[11];
    const float* pb1    = (const float*)d_in[12];
    const float* pw2    = (const float*)d_in[13];
    const float* pb2    = (const float*)d_in[14];
    float* out = (float*)d_out;

    const int smem = (HH * HH + BM * LDA) * sizeof(float);   // 107776 B
    cudaFuncSetAttribute(k_gemm, cudaFuncAttributeMaxDynamicSharedMemorySize, smem);

    const int gemm_grid = (NN + BM - 1) / BM;   // 1250

    // degree / norm / CSR build
    k_init <<<(NN + 255) / 256, 256>>>();
    k_count<<<(EE + 255) / 256, 256>>>(ei + EE);
    k_rsqrt<<<(NN + 255) / 256, 256>>>();
    k_scan1<<<SCAN_BLOCKS, 256>>>();
    k_scan2<<<1, 32>>>();
    k_scan3<<<SCAN_BLOCKS, 256>>>();
    k_fill <<<(EE + 255) / 256, 256>>>(ei, ei + EE);

    // 3 GCN layers (separate apply — full-occupancy streaming)
    for (int i = 0; i < 3; i++) {
        const float* A = (i == 0) ? x : nullptr;   // nullptr -> g_h (device-side)
        k_gemm<<<gemm_grid, 256, smem>>>(A, conv_w + i * HH * HH, conv_b + i * HH,
                                         nullptr, nullptr, 0);
        k_aggregate<<<AGG_BLOCKS, 256>>>();
        k_bnfin<<<1, 128>>>(bn_g + i * HH, bn_b + i * HH);
        k_apply<<<(NN * 32 + 255) / 256, 256>>>(i > 0 ? 1 : 0);
    }

    // attention GEMM with fused score epilogue
    k_gemm<<<gemm_grid, 256, smem>>>(nullptr, aw1, ab1, aw2, ab2, 1);

    // pooling
    k_gstart<<<GG, 128>>>(batch);
    k_pool<<<GG * 8, 128>>>();

    // final MLP
    k_mlp<<<GG, 128>>>(pw1, pb1, pw2, pb2, out);
}

// round 8
// speedup vs baseline: 1.4148x; 1.4148x over previous
#include <cuda_runtime.h>
#include <math.h>

#define NN 100000
#define EE 1600000
#define HH 128
#define GG 64
#define SCAN_BLOCKS 391            // ceil(NN/256)

// ---------------- scratch (device globals; allocation-free) ----------------
__device__ float g_dinv[NN];
__device__ int   g_deg[NN];
__device__ int   g_csr_off[NN + 1];
__device__ int   g_csr_pos[NN];
__device__ int   g_csr_src[EE];
__device__ int   g_part[SCAN_BLOCKS];
__device__ float g_h[NN * HH];
__device__ float g_zs[NN * HH];
__device__ float g_agg[NN * HH];
__device__ float g_sum[HH];
__device__ float g_sumsq[HH];
__device__ float g_scale[HH];
__device__ float g_shift[HH];
__device__ float g_esc[NN];
__device__ float g_sumexp;
__device__ int   g_gstart[GG + 1];
__device__ float g_pooled[GG * HH];

// ---------------- f32x2 helpers (Blackwell packed FFMA2) ----------------
__device__ __forceinline__ unsigned long long dup2(float v) {
    unsigned long long r;
    unsigned int b = __float_as_uint(v);
    asm("mov.b64 %0, {%1, %1};" : "=l"(r) : "r"(b));
    return r;
}
__device__ __forceinline__ void fma2(unsigned long long& d, unsigned long long a,
                                     unsigned long long b) {
    asm("fma.rn.f32x2 %0, %1, %2, %3;" : "=l"(d) : "l"(a), "l"(b), "l"(d));
}
__device__ __forceinline__ float2 unpack2(unsigned long long v) {
    float2 r;
    asm("mov.b64 {%0, %1}, %2;" : "=f"(r.x), "=f"(r.y) : "l"(v));
    return r;
}

// ---------------- init / degree ----------------
__global__ void k_init() {
    int i = blockIdx.x * blockDim.x + threadIdx.x;
    if (i < NN) g_deg[i] = 0;
    if (i == 0) g_sumexp = 0.0f;
}

__global__ void k_count(const int* __restrict__ edst) {
    int e = blockIdx.x * blockDim.x + threadIdx.x;
    if (e < EE) atomicAdd(&g_deg[edst[e]], 1);
}

__global__ void k_rsqrt() {
    int i = blockIdx.x * blockDim.x + threadIdx.x;
    if (i < NN) g_dinv[i] = rsqrtf((float)g_deg[i] + 1.0f);   // +1 self loop
}

// ---------------- CSR build ----------------
__global__ __launch_bounds__(256) void k_scan1() {
    __shared__ int sh[256];
    int i = blockIdx.x * 256 + threadIdx.x;
    sh[threadIdx.x] = (i < NN) ? g_deg[i] : 0;
    __syncthreads();
    for (int s = 128; s > 0; s >>= 1) {
        if (threadIdx.x < s) sh[threadIdx.x] += sh[threadIdx.x + s];
        __syncthreads();
    }
    if (threadIdx.x == 0) g_part[blockIdx.x] = sh[0];
}

__global__ void k_scan2() {
    if (threadIdx.x == 0) {
        int run = 0;
        for (int b = 0; b < SCAN_BLOCKS; b++) {
            int v = g_part[b];
            g_part[b] = run;
            run += v;
        }
        g_csr_off[NN] = run;    // == EE
    }
}

__global__ __launch_bounds__(256) void k_scan3() {
    __shared__ int sh[256];
    int i = blockIdx.x * 256 + threadIdx.x;
    int v = (i < NN) ? g_deg[i] : 0;
    sh[threadIdx.x] = v;
    __syncthreads();
    for (int s = 1; s < 256; s <<= 1) {
        int t = (threadIdx.x >= s) ? sh[threadIdx.x - s] : 0;
        __syncthreads();
        sh[threadIdx.x] += t;
        __syncthreads();
    }
    if (i < NN) {
        int excl = sh[threadIdx.x] - v + g_part[blockIdx.x];
        g_csr_off[i] = excl;
        g_csr_pos[i] = excl;
    }
}

__global__ __launch_bounds__(256) void k_fill(const int* __restrict__ esrc,
                                              const int* __restrict__ edst) {
    int e = blockIdx.x * blockDim.x + threadIdx.x;
    if (e >= EE) return;
    int d = edst[e];
    int p = atomicAdd(&g_csr_pos[d], 1);
    g_csr_src[p] = esrc[e];
}

// ---------------- GEMM: z = A(N,128) @ W(128,128) --------------------------
// BM=128, 8x8 microtile, FFMA2 (R4-proven shape).
// mode 0: g_zs = z*dinv[row];  g_agg = z*dinv^2 + bias[c]
// mode 1: fused attention score: g_esc[row] = exp(tanh(z+bias)·w2 + b2); sum->g_sumexp
#define BM 128
#define LDA 132
__global__ __launch_bounds__(256) void k_gemm(
    const float* __restrict__ Ain, const float* __restrict__ W,
    const float* __restrict__ bias,
    const float* __restrict__ w2, const float* __restrict__ b2,
    int mode)
{
    const float* A = (Ain == nullptr) ? g_h : Ain;
    extern __shared__ float sm[];
    float* sW = sm;                 // 128*128
    float* sA = sm + HH * HH;       // BM*LDA
    __shared__ float sh_e;
    int tid = threadIdx.x;
    int row0 = blockIdx.x * BM;
    if (tid == 0) sh_e = 0.0f;

    // load W (16384 floats = 4096 float4)
    {
        const float4* W4 = (const float4*)W;
        float4* sW4 = (float4*)sW;
#pragma unroll
        for (int t = 0; t < 16; t++) sW4[tid + t * 256] = W4[tid + t * 256];
    }
    // load A tile (128 rows x 128)
    {
#pragma unroll
        for (int t = 0; t < 16; t++) {
            int idx = tid + t * 256;          // 0..4095
            int r = idx >> 5, c4 = idx & 31;
            if (row0 + r < NN) {
                float4 v = *(const float4*)&A[(size_t)(row0 + r) * HH + c4 * 4];
                *(float4*)&sA[r * LDA + c4 * 4] = v;
            }
        }
    }
    __syncthreads();

    int tx = tid & 15, ty = tid >> 4;
    int cbase = tx * 8;
    unsigned long long acc[8][4];
#pragma unroll
    for (int i = 0; i < 8; i++)
#pragma unroll
        for (int j = 0; j < 4; j++) acc[i][j] = 0ull;

#pragma unroll 4
    for (int k0 = 0; k0 < HH; k0 += 4) {
        float4 a[8];
#pragma unroll
        for (int i = 0; i < 8; i++)
            a[i] = *(float4*)&sA[(ty + i * 16) * LDA + k0];
#pragma unroll
        for (int kk = 0; kk < 4; kk++) {
            ulonglong2 b0 = *(ulonglong2*)&sW[(k0 + kk) * HH + cbase];
            ulonglong2 b1 = *(ulonglong2*)&sW[(k0 + kk) * HH + cbase + 4];
#pragma unroll
            for (int i = 0; i < 8; i++) {
                unsigned long long ad = dup2((&a[i].x)[kk]);
                fma2(acc[i][0], ad, b0.x);
                fma2(acc[i][1], ad, b0.y);
                fma2(acc[i][2], ad, b1.x);
                fma2(acc[i][3], ad, b1.y);
            }
        }
    }

    float4 bv0 = ((const float4*)bias)[tx * 2];
    float4 bv1 = ((const float4*)bias)[tx * 2 + 1];
    float4 wv0, wv1;
    float b2v = 0.0f, esum = 0.0f;
    if (mode == 1) {
        wv0 = ((const float4*)w2)[tx * 2];
        wv1 = ((const float4*)w2)[tx * 2 + 1];
        b2v = b2[0];
    }

#pragma unroll
    for (int i = 0; i < 8; i++) {
        int row = row0 + ty + i * 16;
        float2 p0 = unpack2(acc[i][0]);
        float2 p1 = unpack2(acc[i][1]);
        float2 p2 = unpack2(acc[i][2]);
        float2 p3 = unpack2(acc[i][3]);
        float z[8] = {p0.x, p0.y, p1.x, p1.y, p2.x, p2.y, p3.x, p3.y};
        if (mode == 0) {
            if (row < NN) {
                size_t off = (size_t)row * HH + cbase;
                float di = g_dinv[row];
                float di2 = di * di;
                float4 z0 = make_float4(z[0] * di, z[1] * di, z[2] * di, z[3] * di);
                float4 z1 = make_float4(z[4] * di, z[5] * di, z[6] * di, z[7] * di);
                *(float4*)&g_zs[off]     = z0;
                *(float4*)&g_zs[off + 4] = z1;
                float4 q0 = make_float4(z[0] * di2 + bv0.x, z[1] * di2 + bv0.y,
                                        z[2] * di2 + bv0.z, z[3] * di2 + bv0.w);
                float4 q1 = make_float4(z[4] * di2 + bv1.x, z[5] * di2 + bv1.y,
                                        z[6] * di2 + bv1.z, z[7] * di2 + bv1.w);
                *(float4*)&g_agg[off]     = q0;
                *(float4*)&g_agg[off + 4] = q1;
            }
        } else {
            float t0 = tanhf(z[0] + bv0.x), t1 = tanhf(z[1] + bv0.y);
            float t2 = tanhf(z[2] + bv0.z), t3 = tanhf(z[3] + bv0.w);
            float t4 = tanhf(z[4] + bv1.x), t5 = tanhf(z[5] + bv1.y);
            float t6 = tanhf(z[6] + bv1.z), t7 = tanhf(z[7] + bv1.w);
            float part = t0 * wv0.x + t1 * wv0.y + t2 * wv0.z + t3 * wv0.w
                       + t4 * wv1.x + t5 * wv1.y + t6 * wv1.z + t7 * wv1.w;
#pragma unroll
            for (int off16 = 8; off16; off16 >>= 1)
                part += __shfl_xor_sync(0xffffffffu, part, off16);
            if ((tx == 0) && row < NN) {
                float e = expf(part + b2v);
                g_esc[row] = e;
                esum += e;
            }
        }
    }

    if (mode == 1) {
        if (tx == 0) atomicAdd(&sh_e, esum);
        __syncthreads();
        if (tid == 0) atomicAdd(&g_sumexp, sh_e);
    }
}

// ---------------- aggregate (CSR gather) + fused BN stats ----------------
// one warp per dst node (grid-stride) — R4-proven inner loop
#define AGG_BLOCKS 1184
__global__ __launch_bounds__(256) void k_aggregate() {
    int tid = threadIdx.x;
    int lane = tid & 31, warp = tid >> 5;
    int gw = blockIdx.x * 8 + warp;
    int nw = gridDim.x * 8;
    float4 s4 = make_float4(0, 0, 0, 0);
    float4 q4 = make_float4(0, 0, 0, 0);

    for (int node = gw; node < NN; node += nw) {
        int beg = g_csr_off[node], end = g_csr_off[node + 1];
        float4 acc = make_float4(0, 0, 0, 0);
        for (int base = beg; base < end; base += 32) {
            int idx = base + lane;
            int s = (idx < end) ? g_csr_src[idx] : 0;
            int cnt = min(32, end - base);
            for (int j = 0; j < cnt; j++) {
                int ss = __shfl_sync(0xffffffffu, s, j);
                float4 v = *(const float4*)&g_zs[(size_t)ss * HH + lane * 4];
                acc.x += v.x; acc.y += v.y; acc.z += v.z; acc.w += v.w;
            }
        }
        float di = g_dinv[node];
        float* rowp = &g_agg[(size_t)node * HH + lane * 4];
        float4 r = *(float4*)rowp;
        r.x += di * acc.x; r.y += di * acc.y; r.z += di * acc.z; r.w += di * acc.w;
        *(float4*)rowp = r;
        s4.x += r.x; s4.y += r.y; s4.z += r.z; s4.w += r.w;
        q4.x += r.x * r.x; q4.y += r.y * r.y; q4.z += r.z * r.z; q4.w += r.w * r.w;
    }

    __shared__ float sh[8][HH];
    ((float4*)sh[warp])[lane] = s4;
    __syncthreads();
    if (tid < HH) {
        float t = 0.0f;
#pragma unroll
        for (int w = 0; w < 8; w++) t += sh[w][tid];
        atomicAdd(&g_sum[tid], t);
    }
    __syncthreads();
    ((float4*)sh[warp])[lane] = q4;
    __syncthreads();
    if (tid < HH) {
        float t = 0.0f;
#pragma unroll
        for (int w = 0; w < 8; w++) t += sh[w][tid];
        atomicAdd(&g_sumsq[tid], t);
    }
}

// ---------------- batchnorm finalize / apply ----------------
__global__ void k_bnfin(const float* __restrict__ gamma, const float* __restrict__ beta) {
    int c = threadIdx.x;
    float mean = g_sum[c] / (float)NN;
    float var = g_sumsq[c] / (float)NN - mean * mean;
    float sc = rsqrtf(var + 1e-5f) * gamma[c];
    g_scale[c] = sc;
    g_shift[c] = beta[c] - mean * sc;
    g_sum[c] = 0.0f;
    g_sumsq[c] = 0.0f;
}

__global__ __launch_bounds__(256) void k_apply(int residual) {
    int i4 = blockIdx.x * blockDim.x + threadIdx.x;   // over NN*32 float4s
    if (i4 >= NN * 32) return;
    int c4 = i4 & 31;
    float4 v  = ((const float4*)g_agg)[i4];
    float4 sc = ((const float4*)g_scale)[c4];
    float4 sf = ((const float4*)g_shift)[c4];
    float4 r;
    r.x = fmaxf(v.x * sc.x + sf.x, 0.0f);
    r.y = fmaxf(v.y * sc.y + sf.y, 0.0f);
    r.z = fmaxf(v.z * sc.z + sf.z, 0.0f);
    r.w = fmaxf(v.w * sc.w + sf.w, 0.0f);
    if (residual) {
        float4 hv = ((const float4*)g_h)[i4];
        r.x += hv.x; r.y += hv.y; r.z += hv.z; r.w += hv.w;
    }
    ((float4*)g_h)[i4] = r;
}

// ---------------- graph offsets + zero pooled ----------------
__global__ void k_gstart(const int* __restrict__ batch) {
    int g = blockIdx.x, c = threadIdx.x;
    g_pooled[g * HH + c] = 0.0f;
    if (c == 0) {
        int lo = 0, hi = NN;
        while (lo < hi) {
            int m = (lo + hi) >> 1;
            if (batch[m] < g) lo = m + 1; else hi = m;
        }
        g_gstart[g] = lo;
        if (g == 0) g_gstart[GG] = NN;
    }
}

// ---------------- pooling (weighted sums) ----------------
__global__ void k_pool() {
    int g = blockIdx.x >> 3;
    int part = blockIdx.x & 7;
    int s = g_gstart[g], e = g_gstart[g + 1];
    int c = threadIdx.x;
    float acc = 0.0f;
    for (int r = s + part; r < e; r += 8)
        acc += g_h[(size_t)r * HH + c] * g_esc[r];
    atomicAdd(&g_pooled[g * HH + c], acc);
}

// ---------------- final MLP ----------------
__global__ void k_mlp(const float* __restrict__ W1, const float* __restrict__ b1,
                      const float* __restrict__ W2, const float* __restrict__ b2,
                      float* __restrict__ out)
{
    __shared__ float p[HH];
    __shared__ float t[HH];
    int g = blockIdx.x, c = threadIdx.x;
    int cnt = g_gstart[g + 1] - g_gstart[g];
    if (cnt < 1) cnt = 1;
    float inv = 1.0f / (g_sumexp * (float)cnt);
    p[c] = g_pooled[g * HH + c] * inv;
    __syncthreads();
    float acc = b1[c];
    for (int k = 0; k < HH; k++) acc += p[k] * W1[k * HH + c];
    t[c] = fmaxf(acc, 0.0f);
    __syncthreads();
    float acc2 = b2[c];
    for (int k = 0; k < HH; k++) acc2 += t[k] * W2[k * HH + c];
    out[g * HH + c] = acc2;
}

// ---------------- host ----------------
extern "C" void kernel_launch(void* const* d_in, const int* in_sizes, int n_in,
                              void* d_out, int out_size)
{
    const float* x      = (const float*)d_in[0];
    const int*   ei     = (const int*)d_in[1];   // [2, E] int32
    const int*   batch  = (const int*)d_in[2];
    const float* conv_w = (const float*)d_in[3];       // [3,128,128]
    const float* conv_b = (const float*)d_in[4];       // [3,128]
    const float* bn_g   = (const float*)d_in[5];
    const float* bn_b   = (const float*)d_in[6];
    const float* aw1    = (const float*)d_in[7];
    const float* ab1    = (const float*)d_in[8];
    const float* aw2    = (const float*)d_in[9];
    const float* ab2    = (const float*)d_in[10];
    const float* pw1    = (const float*)d_in[11];
    const float* pb1    = (const float*)d_in[12];
    const float* pw2    = (const float*)d_in[13];
    const float* pb2    = (const float*)d_in[14];
    float* out = (float*)d_out;

    const int smem = (HH * HH + BM * LDA) * sizeof(float);   // 133120 B
    cudaFuncSetAttribute(k_gemm, cudaFuncAttributeMaxDynamicSharedMemorySize, smem);

    const int gemm_grid = (NN + BM - 1) / BM;   // 782

    // degree / norm / CSR build
    k_init <<<(NN + 255) / 256, 256>>>();
    k_count<<<(EE + 255) / 256, 256>>>(ei + EE);
    k_rsqrt<<<(NN + 255) / 256, 256>>>();
    k_scan1<<<SCAN_BLOCKS, 256>>>();
    k_scan2<<<1, 32>>>();
    k_scan3<<<SCAN_BLOCKS, 256>>>();
    k_fill <<<(EE + 255) / 256, 256>>>(ei, ei + EE);

    // 3 GCN layers (separate apply — full-occupancy streaming)
    for (int i = 0; i < 3; i++) {
        const float* A = (i == 0) ? x : nullptr;   // nullptr -> g_h (device-side)
        k_gemm<<<gemm_grid, 256, smem>>>(A, conv_w + i * HH * HH, conv_b + i * HH,
                                         nullptr, nullptr, 0);
        k_aggregate<<<AGG_BLOCKS, 256>>>();
        k_bnfin<<<1, 128>>>(bn_g + i * HH, bn_b + i * HH);
        k_apply<<<(NN * 32 + 255) / 256, 256>>>(i > 0 ? 1 : 0);
    }

    // attention GEMM with fused score epilogue (kills k_score + 51MB re-read)
    k_gemm<<<gemm_grid, 256, smem>>>(nullptr, aw1, ab1, aw2, ab2, 1);

    // pooling
    k_gstart<<<GG, 128>>>(batch);
    k_pool<<<GG * 8, 128>>>();

    // final MLP
    k_mlp<<<GG, 128>>>(pw1, pb1, pw2, pb2, out);
}